// round 15
// baseline (speedup 1.0000x reference)
#include <cuda_runtime.h>
#include <cuda_bf16.h>

// -------- constants from the reference --------
#define POOL_SIZE   32
#define PROMPT_LEN  32
#define NCTX        32
#define EMBED       768
#define TOP_K       5
#define N_CLS       1000
#define SUFFIX_LEN  12
#define EMBED_F4    (EMBED / 4)          // 192
#define CLS_F4      14784u               // 77*192
#define PROMPTS_F4  14784000u            // 1000*14784
#define SUF_F4      2304u                // 12*192

// Region A (selection-independent): 1000x45 rows + pool/key = 8,842,752 f4
#define NA_PROMPT   8640000u
#define ROWS45_F4   8640u                // 45*192
// Region B (combined broadcast): 1000x32x192 = 6,144,000 f4
#define CMBCLS_F4   6144u                // 32*192

#define TILE_F4     1536u                // 256 threads x 6 f4
#define SEL_BLOCKS  32u
#define A_TILES     5757u                // exact
#define B_TILES     4000u                // exact
#define A_HEAD      3557u                // pure-A prologue tiles
#define MIX_GROUPS  200u                 // groups of (11 A + 20 B)
#define GRID_TOTAL  (SEL_BLOCKS + A_TILES + B_TILES)     // 9789

// -------- device scratch / sync (zero-init at load) --------
__device__ float4   g_combined4[PROMPT_LEN * EMBED_F4];
__device__ unsigned g_selctr;
__device__ int      g_flag;
__device__ unsigned g_doneB;

// ---- region A tile: prefix/ctx/suffix/pool/key ----
__device__ __forceinline__
void do_tile_A(unsigned tile, int t,
               const float4* __restrict__ pre4,
               const float4* __restrict__ suf4,
               const float4* __restrict__ ctx4,
               const float4* __restrict__ pool4,
               const float4* __restrict__ key4,
               float4* __restrict__ out)
{
    const unsigned base = tile * TILE_F4 + (unsigned)t;
    #pragma unroll
    for (int i = 0; i < 6; ++i) {
        const unsigned idx = base + (unsigned)i * 256u;
        float4 v;
        unsigned o;
        if (idx < NA_PROMPT) {
            const unsigned c   = idx / ROWS45_F4;        // magic-multiply
            const unsigned rem = idx - c * ROWS45_F4;
            const unsigned r   = rem / EMBED_F4;
            const unsigned col = rem - r * EMBED_F4;
            if (r == 0u) {
                v = __ldcs(&pre4[c * EMBED_F4 + col]);
                o = c * CLS_F4 + col;
            } else if (r <= 32u) {
                v = __ldg(&ctx4[(r - 1u) * EMBED_F4 + col]);   // reused 1000x
                o = c * CLS_F4 + (r + 32u) * EMBED_F4 + col;
            } else {
                v = __ldcs(&suf4[c * SUF_F4 + (r - 33u) * EMBED_F4 + col]);
                o = c * CLS_F4 + (r + 32u) * EMBED_F4 + col;
            }
        } else {
            const unsigned q = idx - NA_PROMPT;          // pool then key
            v = (q < 196608u) ? __ldcs(&pool4[q]) : __ldcs(&key4[q - 196608u]);
            o = PROMPTS_F4 + q;
        }
        __stcs(&out[o], v);
    }
}

// ---- region B tile: combined broadcast ----
__device__ __forceinline__
void do_tile_B(unsigned tile, int t, float4* __restrict__ out)
{
    const unsigned base = tile * TILE_F4 + (unsigned)t;
    #pragma unroll
    for (int i = 0; i < 6; ++i) {
        const unsigned idx = base + (unsigned)i * 256u;
        const unsigned c   = idx / CMBCLS_F4;            // magic-multiply
        const unsigned rem = idx - c * CMBCLS_F4;
        __stcs(&out[c * CLS_F4 + EMBED_F4 + rem], __ldg(&g_combined4[rem]));
    }
}

// ============================================================
__global__ __launch_bounds__(256, 6)
void k_all(const float4* __restrict__ x4,
           const float4* __restrict__ key4,
           const float4* __restrict__ pool4,
           const float4* __restrict__ aw4,
           const float*  __restrict__ ab,
           const float4* __restrict__ pre4,
           const float4* __restrict__ suf4,
           const float4* __restrict__ ctx4,
           float4* __restrict__ out)
{
    const unsigned bid = blockIdx.x;
    const int t = threadIdx.x;

    // ========================================================
    // blocks 0..31: selection + gating for token position bid
    // (wave-1 resident; register-tightened to live near the 42-reg cap)
    // ========================================================
    if (bid < SEL_BLOCKS) {
        __shared__ float4 qs4[EMBED_F4];
        __shared__ float  sims[POOL_SIZE];
        __shared__ int    idxs[TOP_K];
        __shared__ float  part[6][TOP_K];
        __shared__ float  wt_s[TOP_K];

        const int w = t >> 5, lane = t & 31;
        const int b = (int)bid;

        // L2-prefetch the 32 candidate pool rows for position b (issued first)
        for (int i = t; i < 32 * 24; i += 256) {
            const int p = i / 24, line = i - p * 24;
            const float4* addr = pool4 + (p * PROMPT_LEN + b) * EMBED_F4 + line * 8;
            asm volatile("prefetch.global.L2 [%0];" :: "l"(addr));
        }

        // q = sum over 16 frames (mean scale & q-norm don't affect top-k)
        if (t < EMBED_F4) {
            float4 s = make_float4(0.f, 0.f, 0.f, 0.f);
            #pragma unroll 4
            for (int f = 0; f < 16; ++f) {
                float4 v = __ldg(&x4[f * EMBED_F4 + t]);
                s.x += v.x; s.y += v.y; s.z += v.z; s.w += v.w;
            }
            qs4[t] = s;
        }
        __syncthreads();

        // all 32 sims, redundantly per block: 8 warps x 4 keys (serialized
        // outer loop to bound register pressure under the occupancy cap)
        #pragma unroll 1
        for (int j = 0; j < 4; ++j) {
            const int p = w + 8 * j;
            const float4* kp = key4 + p * EMBED_F4;
            float dot = 0.f, nrm = 0.f;
            #pragma unroll
            for (int i = 0; i < 6; ++i) {
                const int c = lane + i * 32;
                float4 kv = __ldg(&kp[c]), qv = qs4[c];
                dot += kv.x*qv.x + kv.y*qv.y + kv.z*qv.z + kv.w*qv.w;
                nrm += kv.x*kv.x + kv.y*kv.y + kv.z*kv.z + kv.w*kv.w;
            }
            #pragma unroll
            for (int o = 16; o; o >>= 1) {
                dot += __shfl_down_sync(0xffffffffu, dot, o);
                nrm += __shfl_down_sync(0xffffffffu, nrm, o);
            }
            if (lane == 0) sims[p] = dot * rsqrtf(nrm);
        }
        __syncthreads();

        // top-5, strict '>' = lowest index wins ties (matches jax.lax.top_k)
        if (t == 0) {
            unsigned usedmask = 0u;
            for (int k = 0; k < TOP_K; ++k) {
                int best = 0; float bv = -3.0e38f;
                #pragma unroll
                for (int p = 0; p < POOL_SIZE; ++p)
                    if (!((usedmask >> p) & 1u) && sims[p] > bv) { bv = sims[p]; best = p; }
                usedmask |= 1u << best;
                idxs[k] = best;
            }
        }
        __syncthreads();

        // gates + weighted sum for position b (first 192 threads; two-pass
        // row reloads keep live registers low — second pass is L1-hit)
        if (t < EMBED_F4) {
            float4 av = __ldg(&aw4[t]);
            float dots[TOP_K];
            #pragma unroll 1
            for (int k = 0; k < TOP_K; ++k) {
                const float4* row = pool4 + (idxs[k] * PROMPT_LEN + b) * EMBED_F4;
                float4 rv = __ldg(&row[t]);              // L2 hit (prefetched)
                dots[k] = rv.x*av.x + rv.y*av.y + rv.z*av.z + rv.w*av.w;
            }
            #pragma unroll
            for (int k = 0; k < TOP_K; ++k) {
                #pragma unroll
                for (int o = 16; o; o >>= 1)
                    dots[k] += __shfl_down_sync(0xffffffffu, dots[k], o);
            }
            if (lane == 0) {
                #pragma unroll
                for (int k = 0; k < TOP_K; ++k) part[w][k] = dots[k];
            }
            __syncthreads();
            if (t < TOP_K) {
                float d = 0.f;
                #pragma unroll
                for (int i = 0; i < 6; ++i) d += part[i][t];
                wt_s[t] = 1.f / (1.f + __expf(-(d + ab[0])));
            }
            __syncthreads();

            float4 acc = make_float4(0.f, 0.f, 0.f, 0.f);
            #pragma unroll 1
            for (int k = 0; k < TOP_K; ++k) {
                const float wk = wt_s[k];
                const float4* row = pool4 + (idxs[k] * PROMPT_LEN + b) * EMBED_F4;
                float4 rv = __ldg(&row[t]);              // L1 hit
                acc.x += wk*rv.x; acc.y += wk*rv.y;
                acc.z += wk*rv.z; acc.w += wk*rv.w;
            }
            g_combined4[b * EMBED_F4 + t] = acc;
        } else {
            __syncthreads();
            __syncthreads();
        }

        __syncthreads();
        if (t == 0) {
            __threadfence();
            unsigned prev = atomicAdd(&g_selctr, 1u);
            if (prev == SEL_BLOCKS - 1u) atomicExch(&g_flag, 1);
        }
        return;
    }

    // ========================================================
    // A-head: blocks 32 .. 32+A_HEAD-1 -> pure region-A tiles
    // ========================================================
    if (bid < SEL_BLOCKS + A_HEAD) {
        do_tile_A(bid - SEL_BLOCKS, t, pre4, suf4, ctx4, pool4, key4, out);
        return;
    }

    // ========================================================
    // Mixed region: groups of 31 blocks = 11 A-tiles + 20 B-tiles.
    // B blocks become resident only after ~4 waves of A-head
    // retirements -> flag long set; spin is effectively free.
    // ========================================================
    {
        const unsigned k = bid - SEL_BLOCKS - A_HEAD;
        const unsigned g = k / 31u;
        const unsigned r = k - g * 31u;
        if (r < 11u) {
            do_tile_A(A_HEAD + g * 11u + r, t, pre4, suf4, ctx4, pool4, key4, out);
            return;
        }

        // B tile
        if (t == 0) {
            while (atomicAdd(&g_flag, 0) == 0) __nanosleep(128);
        }
        __syncthreads();
        __threadfence();

        do_tile_B(g * 20u + (r - 11u), t, out);

        // replay reset: last B block zeroes all sync state
        __syncthreads();
        if (t == 0) {
            __threadfence();
            unsigned prev = atomicAdd(&g_doneB, 1u);
            if (prev == B_TILES - 1u) {
                g_doneB = 0u; g_selctr = 0u; g_flag = 0;
            }
        }
    }
}

// ============================================================
extern "C" void kernel_launch(void* const* d_in, const int* in_sizes, int n_in,
                              void* d_out, int out_size)
{
    const float* x_embed      = (const float*)d_in[0];
    const float* prompt_pool  = (const float*)d_in[1];
    const float* prompt_key   = (const float*)d_in[2];
    const float* alpha_w      = (const float*)d_in[3];
    const float* alpha_b      = (const float*)d_in[4];
    const float* ctx          = (const float*)d_in[5];
    const float* token_prefix = (const float*)d_in[6];
    const float* token_suffix = (const float*)d_in[7];
    // d_in[8] = train_flag: the penalty is a positive scalar on sims ->
    // top-k ordering (and therefore the output) is unchanged; safely ignored.

    k_all<<<GRID_TOTAL, 256>>>((const float4*)x_embed,
                               (const float4*)prompt_key,
                               (const float4*)prompt_pool,
                               (const float4*)alpha_w,
                               alpha_b,
                               (const float4*)token_prefix,
                               (const float4*)token_suffix,
                               (const float4*)ctx,
                               (float4*)d_out);
}

// round 16
// speedup vs baseline: 1.0362x; 1.0362x over previous
#include <cuda_runtime.h>
#include <cuda_bf16.h>

// -------- constants from the reference --------
#define POOL_SIZE   32
#define PROMPT_LEN  32
#define NCTX        32
#define EMBED       768
#define TOP_K       5
#define N_CLS       1000
#define SUFFIX_LEN  12
#define EMBED_F4    (EMBED / 4)          // 192
#define CLS_F4      14784u               // 77*192
#define PROMPTS_F4  14784000u            // 1000*14784
#define SUF_F4      2304u                // 12*192

// Region A (selection-independent): 1000x45 rows + pool/key = 8,842,752 f4
#define NA_PROMPT   8640000u
#define ROWS45_F4   8640u                // 45*192
// Region B (combined broadcast): 1000x32x192 = 6,144,000 f4
#define CMBCLS_F4   6144u                // 32*192

#define TILE_F4     1536u                // 256 threads x 6 f4
#define A_BLOCKS    5757u                // 1536*5757 = 8,842,752 exact
#define B_BLOCKS    4000u                // 1536*4000 = 6,144,000 exact

// -------- device scratch (zero-init at load) --------
__device__ float4 g_combined4[PROMPT_LEN * EMBED_F4];

// ============================================================
// kSel: 32 independent blocks x 256 threads, NO inter-block sync.
// Block b: prefetch candidate pool rows, redundantly compute all 32
// sims, top-5, gates + weighted sum for token position b.
// ============================================================
__global__ __launch_bounds__(256, 1)
void kSel(const float4* __restrict__ x4,       // [16,192]
          const float4* __restrict__ key4,     // [32,192]
          const float4* __restrict__ pool4,    // [32,32,192]
          const float4* __restrict__ aw4,      // [192]
          const float*  __restrict__ ab)       // [1]
{
    __shared__ float4 qs4[EMBED_F4];
    __shared__ float  sims[POOL_SIZE];
    __shared__ int    idxs[TOP_K];
    __shared__ float  part[6][TOP_K];
    __shared__ float  wt_s[TOP_K];

    const int t = threadIdx.x;
    const int w = t >> 5, lane = t & 31;
    const int b = blockIdx.x;                  // token position

    // L2-prefetch the 32 candidate pool rows for position b
    for (int i = t; i < 32 * 24; i += 256) {
        const int p = i / 24, line = i - p * 24;
        const float4* addr = pool4 + (p * PROMPT_LEN + b) * EMBED_F4 + line * 8;
        asm volatile("prefetch.global.L2 [%0];" :: "l"(addr));
    }

    // q = sum over 16 frames (mean scale & q-norm don't affect top-k)
    if (t < EMBED_F4) {
        float4 s = make_float4(0.f, 0.f, 0.f, 0.f);
        #pragma unroll
        for (int f = 0; f < 16; ++f) {
            float4 v = __ldg(&x4[f * EMBED_F4 + t]);
            s.x += v.x; s.y += v.y; s.z += v.z; s.w += v.w;
        }
        qs4[t] = s;
    }
    __syncthreads();

    // all 32 sims, redundantly per block: 8 warps x 4 keys
    // sim = (k.q)/||k||  (order-equivalent to cosine similarity)
    #pragma unroll
    for (int j = 0; j < 4; ++j) {
        const int p = w + 8 * j;
        const float4* kp = key4 + p * EMBED_F4;
        float dot = 0.f, nrm = 0.f;
        #pragma unroll
        for (int i = 0; i < 6; ++i) {
            const int c = lane + i * 32;
            float4 kv = __ldg(&kp[c]), qv = qs4[c];
            dot += kv.x*qv.x + kv.y*qv.y + kv.z*qv.z + kv.w*qv.w;
            nrm += kv.x*kv.x + kv.y*kv.y + kv.z*kv.z + kv.w*kv.w;
        }
        #pragma unroll
        for (int o = 16; o; o >>= 1) {
            dot += __shfl_down_sync(0xffffffffu, dot, o);
            nrm += __shfl_down_sync(0xffffffffu, nrm, o);
        }
        if (lane == 0) sims[p] = dot * rsqrtf(nrm);
    }
    __syncthreads();

    // top-5, strict '>' = lowest index wins ties (matches jax.lax.top_k)
    if (t == 0) {
        unsigned usedmask = 0u;
        for (int k = 0; k < TOP_K; ++k) {
            int best = 0; float bv = -3.0e38f;
            #pragma unroll
            for (int p = 0; p < POOL_SIZE; ++p)
                if (!((usedmask >> p) & 1u) && sims[p] > bv) { bv = sims[p]; best = p; }
            usedmask |= 1u << best;
            idxs[k] = best;
        }
    }
    __syncthreads();

    // gates + weighted sum for token position b (first 192 threads)
    if (t < EMBED_F4) {
        const float4* rows[TOP_K];
        #pragma unroll
        for (int k = 0; k < TOP_K; ++k)
            rows[k] = pool4 + (idxs[k] * PROMPT_LEN + b) * EMBED_F4;

        float4 av = __ldg(&aw4[t]);
        float4 rv[TOP_K];
        float dots[TOP_K];
        #pragma unroll
        for (int k = 0; k < TOP_K; ++k) {
            rv[k] = __ldg(&rows[k][t]);          // L2 hit (prefetched)
            dots[k] = rv[k].x*av.x + rv[k].y*av.y + rv[k].z*av.z + rv[k].w*av.w;
        }
        #pragma unroll
        for (int k = 0; k < TOP_K; ++k) {
            #pragma unroll
            for (int o = 16; o; o >>= 1)
                dots[k] += __shfl_down_sync(0xffffffffu, dots[k], o);
        }
        if (lane == 0) {
            #pragma unroll
            for (int k = 0; k < TOP_K; ++k) part[w][k] = dots[k];
        }
        __syncthreads();
        if (t < TOP_K) {
            float d = 0.f;
            #pragma unroll
            for (int i = 0; i < 6; ++i) d += part[i][t];
            wt_s[t] = 1.f / (1.f + __expf(-(d + ab[0])));
        }
        __syncthreads();

        float4 acc = make_float4(0.f, 0.f, 0.f, 0.f);
        #pragma unroll
        for (int k = 0; k < TOP_K; ++k) {
            const float wk = wt_s[k];
            acc.x += wk*rv[k].x; acc.y += wk*rv[k].y;
            acc.z += wk*rv[k].z; acc.w += wk*rv[k].w;
        }
        g_combined4[b * EMBED_F4 + t] = acc;
    } else {
        __syncthreads();
        __syncthreads();
    }
}

// ============================================================
// kC_A: exact-tile copy of the selection-independent region.
// Block i handles f4 range [i*1536, (i+1)*1536) — no loop/bounds.
// ============================================================
__global__ __launch_bounds__(256, 6)
void kC_A(const float4* __restrict__ pre4,
          const float4* __restrict__ suf4,
          const float4* __restrict__ ctx4,
          const float4* __restrict__ pol4,
          const float4* __restrict__ key4,
          float4* __restrict__ out)
{
    const unsigned base = blockIdx.x * TILE_F4 + threadIdx.x;
    #pragma unroll
    for (int i = 0; i < 6; ++i) {
        const unsigned idx = base + (unsigned)i * 256u;
        float4 v;
        unsigned o;
        if (idx < NA_PROMPT) {
            const unsigned c   = idx / ROWS45_F4;        // magic-multiply
            const unsigned rem = idx - c * ROWS45_F4;
            const unsigned r   = rem / EMBED_F4;
            const unsigned col = rem - r * EMBED_F4;
            if (r == 0u) {
                v = __ldcs(&pre4[c * EMBED_F4 + col]);
                o = c * CLS_F4 + col;
            } else if (r <= 32u) {
                v = __ldg(&ctx4[(r - 1u) * EMBED_F4 + col]);   // reused 1000x
                o = c * CLS_F4 + (r + 32u) * EMBED_F4 + col;
            } else {
                v = __ldcs(&suf4[c * SUF_F4 + (r - 33u) * EMBED_F4 + col]);
                o = c * CLS_F4 + (r + 32u) * EMBED_F4 + col;
            }
        } else {
            const unsigned q = idx - NA_PROMPT;          // pool then key
            v = (q < 196608u) ? __ldcs(&pol4[q]) : __ldcs(&key4[q - 196608u]);
            o = PROMPTS_F4 + q;
        }
        __stcs(&out[o], v);
    }
}

// ============================================================
// kC_B: exact-tile broadcast of the 32 combined rows to 1000 classes
// ============================================================
__global__ __launch_bounds__(256, 6)
void kC_B(float4* __restrict__ out)
{
    const unsigned base = blockIdx.x * TILE_F4 + threadIdx.x;
    #pragma unroll
    for (int i = 0; i < 6; ++i) {
        const unsigned idx = base + (unsigned)i * 256u;
        const unsigned c   = idx / CMBCLS_F4;            // magic-multiply
        const unsigned rem = idx - c * CMBCLS_F4;
        __stcs(&out[c * CLS_F4 + EMBED_F4 + rem], __ldg(&g_combined4[rem]));
    }
}

// ============================================================
extern "C" void kernel_launch(void* const* d_in, const int* in_sizes, int n_in,
                              void* d_out, int out_size)
{
    const float* x_embed      = (const float*)d_in[0];
    const float* prompt_pool  = (const float*)d_in[1];
    const float* prompt_key   = (const float*)d_in[2];
    const float* alpha_w      = (const float*)d_in[3];
    const float* alpha_b      = (const float*)d_in[4];
    const float* ctx          = (const float*)d_in[5];
    const float* token_prefix = (const float*)d_in[6];
    const float* token_suffix = (const float*)d_in[7];
    // d_in[8] = train_flag: the penalty is a positive scalar on sims ->
    // top-k ordering (and therefore the output) is unchanged; safely ignored.

    // Side stream + fork/join events, created once on the first (non-capture)
    // correctness call. No device memory is allocated.
    static cudaStream_t s1;
    static cudaEvent_t  eFork, eJoin;
    static int init = 0;
    if (!init) {
        cudaStreamCreateWithFlags(&s1, cudaStreamNonBlocking);
        cudaEventCreateWithFlags(&eFork, cudaEventDisableTiming);
        cudaEventCreateWithFlags(&eJoin, cudaEventDisableTiming);
        init = 1;
    }

    // fork
    cudaEventRecord(eFork, 0);
    cudaStreamWaitEvent(s1, eFork, 0);

    // branch 1 (side): selection, then combined broadcast (96 MB)
    kSel<<<POOL_SIZE, 256, 0, s1>>>((const float4*)x_embed,
                                    (const float4*)prompt_key,
                                    (const float4*)prompt_pool,
                                    (const float4*)alpha_w, alpha_b);
    kC_B<<<B_BLOCKS, 256, 0, s1>>>((float4*)d_out);

    // branch 0 (main): selection-independent region (~180 MB), concurrent
    kC_A<<<A_BLOCKS, 256>>>((const float4*)token_prefix,
                            (const float4*)token_suffix,
                            (const float4*)ctx,
                            (const float4*)prompt_pool,
                            (const float4*)prompt_key,
                            (float4*)d_out);

    // join
    cudaEventRecord(eJoin, s1);
    cudaStreamWaitEvent(0, eJoin, 0);
}

// round 17
// speedup vs baseline: 1.0375x; 1.0013x over previous
#include <cuda_runtime.h>
#include <cuda_bf16.h>

// -------- constants from the reference --------
#define POOL_SIZE   32
#define PROMPT_LEN  32
#define NCTX        32
#define EMBED       768
#define TOP_K       5
#define N_CLS       1000
#define SUFFIX_LEN  12
#define EMBED_F4    (EMBED / 4)          // 192
#define CLS_F4      14784u               // 77*192
#define PROMPTS_F4  14784000u            // 1000*14784
#define SUF_F4      2304u                // 12*192

// Region A (selection-independent): 1000x45 rows + pool/key = 8,842,752 f4
#define NA_PROMPT   8640000u
#define ROWS45_F4   8640u                // 45*192
// Region B (combined broadcast): 1000x32x192 = 6,144,000 f4
#define CMBCLS_F4   6144u                // 32*192

#define TILE_F4     1536u                // 256 threads x 6 f4
#define A_BLOCKS    5757u                // 1536*5757 = 8,842,752 exact
#define B_BLOCKS    4000u                // 1536*4000 = 6,144,000 exact

#define KEYS_F4     (POOL_SIZE * EMBED_F4)    // 6144 f4 = 96 KB
#define KSEL_SMEM   (KEYS_F4 * 16)            // dynamic smem bytes

// -------- device scratch (zero-init at load) --------
__device__ float4 g_combined4[PROMPT_LEN * EMBED_F4];

// ============================================================
// kSel: 32 independent blocks x 256 threads, NO inter-block sync.
// Single global round-trip: x-loads + key->SMEM staging + pool
// prefetches all issued together; sims read keys from SMEM.
// ============================================================
__global__ __launch_bounds__(256, 1)
void kSel(const float4* __restrict__ x4,       // [16,192]
          const float4* __restrict__ key4,     // [32,192]
          const float4* __restrict__ pool4,    // [32,32,192]
          const float4* __restrict__ aw4,      // [192]
          const float*  __restrict__ ab)       // [1]
{
    extern __shared__ float4 key_s[];          // [KEYS_F4] = 96 KB
    __shared__ float4 qs4[EMBED_F4];
    __shared__ float  sims[POOL_SIZE];
    __shared__ int    idxs[TOP_K];
    __shared__ float  part[6][TOP_K];
    __shared__ float  wt_s[TOP_K];

    const int t = threadIdx.x;
    const int w = t >> 5, lane = t & 31;
    const int b = blockIdx.x;                  // token position

    // L2-prefetch the 32 candidate pool rows for position b (fire first)
    for (int i = t; i < 32 * 24; i += 256) {
        const int p = i / 24, line = i - p * 24;
        const float4* addr = pool4 + (p * PROMPT_LEN + b) * EMBED_F4 + line * 8;
        asm volatile("prefetch.global.L2 [%0];" :: "l"(addr));
    }

    // ---- single round trip: keys -> SMEM (all 256 threads, 24 f4 each)
    //      AND q = sum over 16 frames (threads 0..191), issued together
    #pragma unroll
    for (int i = 0; i < 24; ++i)
        key_s[t + i * 256] = __ldg(&key4[t + i * 256]);

    if (t < EMBED_F4) {
        float4 s = make_float4(0.f, 0.f, 0.f, 0.f);
        #pragma unroll
        for (int f = 0; f < 16; ++f) {
            float4 v = __ldg(&x4[f * EMBED_F4 + t]);
            s.x += v.x; s.y += v.y; s.z += v.z; s.w += v.w;
        }
        qs4[t] = s;
    }
    __syncthreads();

    // ---- all 32 sims from SMEM: 8 warps x 4 keys
    //      sim = (k.q)/||k||  (order-equivalent to cosine similarity)
    #pragma unroll
    for (int j = 0; j < 4; ++j) {
        const int p = w + 8 * j;
        const float4* kp = key_s + p * EMBED_F4;
        float dot = 0.f, nrm = 0.f;
        #pragma unroll
        for (int i = 0; i < 6; ++i) {
            const int c = lane + i * 32;
            float4 kv = kp[c], qv = qs4[c];
            dot += kv.x*qv.x + kv.y*qv.y + kv.z*qv.z + kv.w*qv.w;
            nrm += kv.x*kv.x + kv.y*kv.y + kv.z*kv.z + kv.w*kv.w;
        }
        #pragma unroll
        for (int o = 16; o; o >>= 1) {
            dot += __shfl_down_sync(0xffffffffu, dot, o);
            nrm += __shfl_down_sync(0xffffffffu, nrm, o);
        }
        if (lane == 0) sims[p] = dot * rsqrtf(nrm);
    }
    __syncthreads();

    // ---- top-5, strict '>' = lowest index wins ties (matches jax.lax.top_k)
    if (t == 0) {
        unsigned usedmask = 0u;
        for (int k = 0; k < TOP_K; ++k) {
            int best = 0; float bv = -3.0e38f;
            #pragma unroll
            for (int p = 0; p < POOL_SIZE; ++p)
                if (!((usedmask >> p) & 1u) && sims[p] > bv) { bv = sims[p]; best = p; }
            usedmask |= 1u << best;
            idxs[k] = best;
        }
    }
    __syncthreads();

    // ---- gates + weighted sum for token position b (first 192 threads)
    if (t < EMBED_F4) {
        const float4* rows[TOP_K];
        #pragma unroll
        for (int k = 0; k < TOP_K; ++k)
            rows[k] = pool4 + (idxs[k] * PROMPT_LEN + b) * EMBED_F4;

        float4 av = __ldg(&aw4[t]);
        float4 rv[TOP_K];
        float dots[TOP_K];
        #pragma unroll
        for (int k = 0; k < TOP_K; ++k) {
            rv[k] = __ldg(&rows[k][t]);          // L2 hit (prefetched)
            dots[k] = rv[k].x*av.x + rv[k].y*av.y + rv[k].z*av.z + rv[k].w*av.w;
        }
        #pragma unroll
        for (int k = 0; k < TOP_K; ++k) {
            #pragma unroll
            for (int o = 16; o; o >>= 1)
                dots[k] += __shfl_down_sync(0xffffffffu, dots[k], o);
        }
        if (lane == 0) {
            #pragma unroll
            for (int k = 0; k < TOP_K; ++k) part[w][k] = dots[k];
        }
        __syncthreads();
        if (t < TOP_K) {
            float d = 0.f;
            #pragma unroll
            for (int i = 0; i < 6; ++i) d += part[i][t];
            wt_s[t] = 1.f / (1.f + __expf(-(d + ab[0])));
        }
        __syncthreads();

        float4 acc = make_float4(0.f, 0.f, 0.f, 0.f);
        #pragma unroll
        for (int k = 0; k < TOP_K; ++k) {
            const float wk = wt_s[k];
            acc.x += wk*rv[k].x; acc.y += wk*rv[k].y;
            acc.z += wk*rv[k].z; acc.w += wk*rv[k].w;
        }
        g_combined4[b * EMBED_F4 + t] = acc;
    } else {
        __syncthreads();
        __syncthreads();
    }
}

// ============================================================
// kC_A: exact-tile copy of the selection-independent region.
// ============================================================
__global__ __launch_bounds__(256, 6)
void kC_A(const float4* __restrict__ pre4,
          const float4* __restrict__ suf4,
          const float4* __restrict__ ctx4,
          const float4* __restrict__ pol4,
          const float4* __restrict__ key4,
          float4* __restrict__ out)
{
    const unsigned base = blockIdx.x * TILE_F4 + threadIdx.x;
    #pragma unroll
    for (int i = 0; i < 6; ++i) {
        const unsigned idx = base + (unsigned)i * 256u;
        float4 v;
        unsigned o;
        if (idx < NA_PROMPT) {
            const unsigned c   = idx / ROWS45_F4;        // magic-multiply
            const unsigned rem = idx - c * ROWS45_F4;
            const unsigned r   = rem / EMBED_F4;
            const unsigned col = rem - r * EMBED_F4;
            if (r == 0u) {
                v = __ldcs(&pre4[c * EMBED_F4 + col]);
                o = c * CLS_F4 + col;
            } else if (r <= 32u) {
                v = __ldg(&ctx4[(r - 1u) * EMBED_F4 + col]);   // reused 1000x
                o = c * CLS_F4 + (r + 32u) * EMBED_F4 + col;
            } else {
                v = __ldcs(&suf4[c * SUF_F4 + (r - 33u) * EMBED_F4 + col]);
                o = c * CLS_F4 + (r + 32u) * EMBED_F4 + col;
            }
        } else {
            const unsigned q = idx - NA_PROMPT;          // pool then key
            v = (q < 196608u) ? __ldcs(&pol4[q]) : __ldcs(&key4[q - 196608u]);
            o = PROMPTS_F4 + q;
        }
        __stcs(&out[o], v);
    }
}

// ============================================================
// kC_B: exact-tile broadcast of the 32 combined rows to 1000 classes
// ============================================================
__global__ __launch_bounds__(256, 6)
void kC_B(float4* __restrict__ out)
{
    const unsigned base = blockIdx.x * TILE_F4 + threadIdx.x;
    #pragma unroll
    for (int i = 0; i < 6; ++i) {
        const unsigned idx = base + (unsigned)i * 256u;
        const unsigned c   = idx / CMBCLS_F4;            // magic-multiply
        const unsigned rem = idx - c * CMBCLS_F4;
        __stcs(&out[c * CLS_F4 + EMBED_F4 + rem], __ldg(&g_combined4[rem]));
    }
}

// ============================================================
extern "C" void kernel_launch(void* const* d_in, const int* in_sizes, int n_in,
                              void* d_out, int out_size)
{
    const float* x_embed      = (const float*)d_in[0];
    const float* prompt_pool  = (const float*)d_in[1];
    const float* prompt_key   = (const float*)d_in[2];
    const float* alpha_w      = (const float*)d_in[3];
    const float* alpha_b      = (const float*)d_in[4];
    const float* ctx          = (const float*)d_in[5];
    const float* token_prefix = (const float*)d_in[6];
    const float* token_suffix = (const float*)d_in[7];
    // d_in[8] = train_flag: the penalty is a positive scalar on sims ->
    // top-k ordering (and therefore the output) is unchanged; safely ignored.

    // High-priority side stream + fork/join events, created once on the
    // first (non-capture) correctness call. No device memory is allocated.
    static cudaStream_t s1;
    static cudaEvent_t  eFork, eJoin;
    static int init = 0;
    if (!init) {
        int loPri, hiPri;
        cudaDeviceGetStreamPriorityRange(&loPri, &hiPri);
        cudaStreamCreateWithPriority(&s1, cudaStreamNonBlocking, hiPri);
        cudaEventCreateWithFlags(&eFork, cudaEventDisableTiming);
        cudaEventCreateWithFlags(&eJoin, cudaEventDisableTiming);
        cudaFuncSetAttribute(kSel, cudaFuncAttributeMaxDynamicSharedMemorySize,
                             KSEL_SMEM);
        init = 1;
    }

    // fork
    cudaEventRecord(eFork, 0);
    cudaStreamWaitEvent(s1, eFork, 0);

    // branch 1 (side, high priority): selection, then combined broadcast
    kSel<<<POOL_SIZE, 256, KSEL_SMEM, s1>>>((const float4*)x_embed,
                                            (const float4*)prompt_key,
                                            (const float4*)prompt_pool,
                                            (const float4*)alpha_w, alpha_b);
    kC_B<<<B_BLOCKS, 256, 0, s1>>>((float4*)d_out);

    // branch 0 (main): selection-independent region (~180 MB), concurrent
    kC_A<<<A_BLOCKS, 256>>>((const float4*)token_prefix,
                            (const float4*)token_suffix,
                            (const float4*)ctx,
                            (const float4*)prompt_pool,
                            (const float4*)prompt_key,
                            (float4*)d_out);

    // join
    cudaEventRecord(eJoin, s1);
    cudaStreamWaitEvent(0, eJoin, 0);
}